// round 6
// baseline (speedup 1.0000x reference)
#include <cuda_runtime.h>
#include <cuda_fp16.h>
#include <cstdint>

#define B_ 64
#define S_ 2048
#define D_ 512
#define U_ 512
#define M_TOT (B_ * S_)
#define MB_CNT (M_TOT / 32)   // 4096 m32-blocks

// ---------------- scratch (__device__ globals: allocation-free rule) ----------
__device__ float g_hd[B_ * U_];
__device__ float g_scores[M_TOT];
__device__ float g_max[B_];
__device__ float g_invsum[B_];
__device__ float g_spart[4 * M_TOT];
__device__ __half g_w1t[U_ * D_];                  // [n][k] f16
__device__ uint4 g_encfrag[(size_t)MB_CNT * 2048]; // [mb][k16(32)][g(2)][lane(32)]
__device__ uint4 g_w1frag[8 * 4096];               // [nb][k16(32)][g(4)][lane(32)]

// ---------------- helpers ----------------------------------------------------
__device__ __forceinline__ uint32_t smem_u32(const void* p) {
    uint32_t a;
    asm("{ .reg .u64 t; cvta.to.shared.u64 t, %1; cvt.u32.u64 %0, t; }" : "=r"(a) : "l"(p));
    return a;
}
__device__ __forceinline__ void ldsm4(uint32_t r[4], uint32_t addr) {
    asm volatile("ldmatrix.sync.aligned.m8n8.x4.shared.b16 {%0,%1,%2,%3}, [%4];"
                 : "=r"(r[0]), "=r"(r[1]), "=r"(r[2]), "=r"(r[3]) : "r"(addr));
}
__device__ __forceinline__ void mma16816(float c[4], const uint32_t* a, const uint32_t* b) {
    asm volatile(
        "mma.sync.aligned.m16n8k16.row.col.f32.f16.f16.f32 "
        "{%0,%1,%2,%3}, {%4,%5,%6,%7}, {%8,%9}, {%0,%1,%2,%3};"
        : "+f"(c[0]), "+f"(c[1]), "+f"(c[2]), "+f"(c[3])
        : "r"(a[0]), "r"(a[1]), "r"(a[2]), "r"(a[3]), "r"(b[0]), "r"(b[1]));
}
__device__ __forceinline__ uint32_t h2u(half2 h) { return *reinterpret_cast<uint32_t*>(&h); }

// ---------------- small kernels ----------------------------------------------
__global__ void zero_out_kernel(float* out) {
    int i = blockIdx.x * blockDim.x + threadIdx.x;
    if (i < B_ * D_) out[i] = 0.0f;
}

// W1 [K][N] f32 -> W1T [N][K] f16 (transpose + convert)
__global__ void w1split_kernel(const float* __restrict__ W1) {
    __shared__ float t[32][33];
    const int n0 = blockIdx.x * 32, k0 = blockIdx.y * 32;
    const int tx = threadIdx.x, ty = threadIdx.y;  // (32, 8)
#pragma unroll
    for (int r = 0; r < 4; r++)
        t[ty + r * 8][tx] = W1[(size_t)(k0 + ty + r * 8) * U_ + n0 + tx];
    __syncthreads();
#pragma unroll
    for (int r = 0; r < 4; r++) {
        const float x = t[tx][ty + r * 8];
        g_w1t[(size_t)(n0 + ty + r * 8) * D_ + k0 + tx] = __float2half_rn(x);
    }
}

__global__ void hd_kernel(const float* __restrict__ dec,
                          const float* __restrict__ W2,
                          const float* __restrict__ b2) {
    __shared__ float ds[D_];
    int b = blockIdx.x;
    int u = threadIdx.x;
    ds[u] = dec[b * D_ + u];
    __syncthreads();
    float a = b2[u];
#pragma unroll 8
    for (int k = 0; k < D_; k++) a = fmaf(ds[k], W2[k * U_ + u], a);
    g_hd[b * U_ + u] = a;
}

// ---------------- prepass: enc f32 -> A fragments (f16) ----------------------
__global__ __launch_bounds__(256)
void encfrag_kernel(const float* __restrict__ enc) {
    __shared__ __align__(16) char sA[8][32 * 80];
    const int lane = threadIdx.x & 31, wid = threadIdx.x >> 5;
    const int mb = blockIdx.x * 8 + wid;
    const float* src = enc + (size_t)mb * 32 * D_;
    char* ws = sA[wid];
    const uint32_t base = smem_u32(ws);
    const uint32_t aoff = ((lane & 7) + ((lane >> 3) & 1) * 8) * 80 + ((lane >> 4) & 1) * 16;
    const int r0 = lane >> 3;        // 0..3
    const int c0 = (lane & 7) * 4;   // f32 col within k32 chunk

    for (int kt = 0; kt < 16; kt++) {
        const int k0 = kt * 32;
#pragma unroll
        for (int i = 0; i < 8; i++) {
            const int row = r0 + i * 4;
            float4 f = *(const float4*)(src + (size_t)row * D_ + k0 + c0);
            half2 h0 = __floats2half2_rn(f.x, f.y);
            half2 h1 = __floats2half2_rn(f.z, f.w);
            *(uint2*)(ws + row * 80 + c0 * 2) = make_uint2(h2u(h0), h2u(h1));
        }
        __syncwarp();
#pragma unroll
        for (int s = 0; s < 2; s++)
#pragma unroll
            for (int g = 0; g < 2; g++) {
                uint32_t r[4];
                ldsm4(r, base + g * 16 * 80 + s * 32 + aoff);
                g_encfrag[(((size_t)mb * 32 + kt * 2 + s) * 2 + g) * 32 + lane] =
                    make_uint4(r[0], r[1], r[2], r[3]);
            }
        __syncwarp();
    }
}

// ---------------- prepass: W1T f16 -> B fragments ----------------------------
__global__ void w1frag_kernel() {
    __shared__ __align__(16) char sB[64 * 80];
    const int lane = threadIdx.x;   // 32 threads
    const int nb = blockIdx.x;      // 0..7
    const uint32_t base = smem_u32(sB);
    const uint32_t boff = ((lane & 7) + ((lane >> 4) & 1) * 8) * 80 + ((lane >> 3) & 1) * 16;
    const int r0 = lane >> 3;       // 0..3
    const int c0 = (lane & 7) * 4;  // half col within k32 chunk

    for (int kt = 0; kt < 16; kt++) {
        const int k0 = kt * 32;
#pragma unroll
        for (int i = 0; i < 16; i++) {
            const int row = r0 + i * 4;   // 0..63
            uint2 v = *(const uint2*)(g_w1t + (size_t)(nb * 64 + row) * D_ + k0 + c0);
            *(uint2*)(sB + row * 80 + c0 * 2) = v;
        }
        __syncwarp();
#pragma unroll
        for (int s = 0; s < 2; s++)
#pragma unroll
            for (int g = 0; g < 4; g++) {
                uint32_t r[4];
                ldsm4(r, base + g * 16 * 80 + s * 32 + boff);
                g_w1frag[((nb * 32 + kt * 2 + s) * 4 + g) * 32 + lane] =
                    make_uint4(r[0], r[1], r[2], r[3]);
            }
        __syncwarp();
    }
}

// ---------------- main score kernel: m64n64 warp tiles, pure LDG + HMMA ------
__global__ __launch_bounds__(128, 2)
void score_frag_kernel(const float* __restrict__ b1, const float* __restrict__ V) {
    __shared__ float cpre[128], vpre[128], ssum[128];
    const int tid = threadIdx.x, lane = tid & 31, wid = tid >> 5;  // 4 warps
    const int wm = wid >> 1, wn = wid & 1;
    const int n0 = blockIdx.x * 128, m0 = blockIdx.y * 128, b = m0 >> 11;

    cpre[tid] = b1[n0 + tid] + g_hd[b * U_ + n0 + tid];
    vpre[tid] = V[n0 + tid];
    ssum[tid] = 0.0f;

    const int mb0 = blockIdx.y * 4 + wm * 2;   // warp covers mb0, mb0+1 (m64)
    const int nb = blockIdx.x * 2 + wn;        // warp covers n64
    const uint4* Ap = g_encfrag + (size_t)mb0 * 2048 + lane;  // +k*64 per k16, +32 per g, +2048 per mb
    const uint4* Bp = g_w1frag + (size_t)nb * 4096 + lane;    // +k*128 per k16, +32 per g

    float acc[4][8][4] = {};   // [m16 tile][n8 tile][frag]

    uint4 a[4], f[4], na[4], nf[4];
    a[0] = Ap[0];    a[1] = Ap[32];
    a[2] = Ap[2048]; a[3] = Ap[2048 + 32];
    f[0] = Bp[0];    f[1] = Bp[32];
    f[2] = Bp[64];   f[3] = Bp[96];

#pragma unroll 1
    for (int k = 0; k < 32; k++) {
        if (k < 31) {
            const uint4* An = Ap + (size_t)(k + 1) * 64;
            const uint4* Bn = Bp + (size_t)(k + 1) * 128;
            na[0] = An[0];    na[1] = An[32];
            na[2] = An[2048]; na[3] = An[2048 + 32];
            nf[0] = Bn[0];    nf[1] = Bn[32];
            nf[2] = Bn[64];   nf[3] = Bn[96];
        }
#pragma unroll
        for (int nq = 0; nq < 4; nq++) {
            const uint32_t* Bq = (const uint32_t*)&f[nq];
#pragma unroll
            for (int mf = 0; mf < 4; mf++) {
                const uint32_t* Aq = (const uint32_t*)&a[mf];
                mma16816(acc[mf][2 * nq + 0], Aq, Bq);
                mma16816(acc[mf][2 * nq + 1], Aq, Bq + 2);
            }
        }
        if (k < 31) {
#pragma unroll
            for (int j = 0; j < 4; j++) { a[j] = na[j]; f[j] = nf[j]; }
        }
    }

    __syncthreads();  // cpre/vpre/ssum ready (also orders epilogue atomics)

    // ---- epilogue: tanh + V-dot, reduce to row partials ----
    const int g = lane >> 2, tg = lane & 3;
    const int n_base = wn * 64;
#pragma unroll
    for (int mf = 0; mf < 4; mf++) {
        float p0 = 0.0f, p1 = 0.0f;
#pragma unroll
        for (int nq = 0; nq < 8; nq++) {
            const int c0 = n_base + nq * 8 + tg * 2;
            const float v0 = vpre[c0], v1 = vpre[c0 + 1];
            const float k0 = cpre[c0], k1 = cpre[c0 + 1];
            p0 += v0 * tanhf(acc[mf][nq][0] + k0) + v1 * tanhf(acc[mf][nq][1] + k1);
            p1 += v0 * tanhf(acc[mf][nq][2] + k0) + v1 * tanhf(acc[mf][nq][3] + k1);
        }
        p0 += __shfl_xor_sync(0xffffffffu, p0, 1);
        p0 += __shfl_xor_sync(0xffffffffu, p0, 2);
        p1 += __shfl_xor_sync(0xffffffffu, p1, 1);
        p1 += __shfl_xor_sync(0xffffffffu, p1, 2);
        if (tg == 0) {
            // row within CTA: wm*64 + mf*16 + g (p0) / +8 (p1); mf tiles: mb pairs
            atomicAdd(&ssum[wm * 64 + mf * 16 + g], p0);
            atomicAdd(&ssum[wm * 64 + mf * 16 + 8 + g], p1);
        }
    }
    __syncthreads();
    g_spart[(size_t)blockIdx.x * M_TOT + m0 + tid] = ssum[tid];
}

// ---------------- softmax stats (combines 4 partials) + context --------------
__global__ void stats_kernel() {
    const int b = blockIdx.x;
    const int tid = threadIdx.x;  // 256
    __shared__ float red[256];
    float m = -1e30f;
    for (int s = tid; s < S_; s += 256) {
        const int i = b * S_ + s;
        const float v = g_spart[i] + g_spart[M_TOT + i] + g_spart[2 * M_TOT + i] + g_spart[3 * M_TOT + i];
        g_scores[i] = v;
        m = fmaxf(m, v);
    }
    red[tid] = m;
    __syncthreads();
    for (int o = 128; o; o >>= 1) {
        if (tid < o) red[tid] = fmaxf(red[tid], red[tid + o]);
        __syncthreads();
    }
    const float mx = red[0];
    __syncthreads();
    float sum = 0.0f;
    for (int s = tid; s < S_; s += 256) sum += expf(g_scores[b * S_ + s] - mx);
    red[tid] = sum;
    __syncthreads();
    for (int o = 128; o; o >>= 1) {
        if (tid < o) red[tid] += red[tid + o];
        __syncthreads();
    }
    if (tid == 0) {
        g_max[b] = mx;
        g_invsum[b] = 1.0f / red[0];
    }
}

__global__ void context_kernel(const float* __restrict__ enc,
                               float* __restrict__ out) {
    __shared__ float attn[128];
    const int b = blockIdx.y;
    const int s0 = blockIdx.x * 128;
    const int tid = threadIdx.x;  // 256
    if (tid < 128)
        attn[tid] = expf(g_scores[b * S_ + s0 + tid] - g_max[b]) * g_invsum[b];
    __syncthreads();
    float acc0 = 0.0f, acc1 = 0.0f;
    const float* base = enc + ((size_t)b * S_ + s0) * D_;
#pragma unroll 4
    for (int s = 0; s < 128; s++) {
        const float w = attn[s];
        acc0 = fmaf(w, base[(size_t)s * D_ + tid], acc0);
        acc1 = fmaf(w, base[(size_t)s * D_ + tid + 256], acc1);
    }
    atomicAdd(&out[b * D_ + tid], acc0);
    atomicAdd(&out[b * D_ + tid + 256], acc1);
}

// ---------------- launch ------------------------------------------------------
extern "C" void kernel_launch(void* const* d_in, const int* in_sizes, int n_in,
                              void* d_out, int out_size) {
    const float* enc = (const float*)d_in[0];
    const float* dec = (const float*)d_in[1];
    const float* W1  = (const float*)d_in[2];
    const float* b1  = (const float*)d_in[3];
    const float* W2  = (const float*)d_in[4];
    const float* b2  = (const float*)d_in[5];
    const float* V   = (const float*)d_in[6];
    // d_in[7] = bv: constant shift, cancels in softmax.
    float* out = (float*)d_out;

    w1split_kernel<<<dim3(16, 16), dim3(32, 8)>>>(W1);
    w1frag_kernel<<<8, 32>>>();
    encfrag_kernel<<<MB_CNT / 8, 256>>>(enc);
    zero_out_kernel<<<(B_ * D_ + 255) / 256, 256>>>(out);
    hd_kernel<<<B_, U_>>>(dec, W2, b2);
    score_frag_kernel<<<dim3(4, M_TOT / 128), 128>>>(b1, V);
    stats_kernel<<<B_, 256>>>();
    context_kernel<<<dim3(S_ / 128, B_), 256>>>(enc, out);
}

// round 7
// speedup vs baseline: 1.3026x; 1.3026x over previous
#include <cuda_runtime.h>
#include <cuda_fp16.h>
#include <cstdint>

#define B_ 64
#define S_ 2048
#define D_ 512
#define U_ 512
#define M_TOT (B_ * S_)
#define MB_CNT (M_TOT / 32)   // 4096 m32-blocks
#define STAGES 5

// ---------------- scratch (__device__ globals: allocation-free rule) ----------
__device__ float g_hd[B_ * U_];
__device__ float g_scores[M_TOT];
__device__ float g_max[B_];
__device__ float g_invsum[B_];
__device__ float g_spart[4 * M_TOT];
__device__ __half g_w1t[U_ * D_];                  // [n][k] f16
__device__ uint4 g_encfrag[(size_t)MB_CNT * 2048]; // [mb][k16(32)][g(2)][lane(32)]
__device__ uint4 g_w1frag[8 * 4096];               // [nb][k16(32)][g(4)][lane(32)]

// ---------------- helpers ----------------------------------------------------
__device__ __forceinline__ uint32_t smem_u32(const void* p) {
    uint32_t a;
    asm("{ .reg .u64 t; cvta.to.shared.u64 t, %1; cvt.u32.u64 %0, t; }" : "=r"(a) : "l"(p));
    return a;
}
__device__ __forceinline__ void cp16(uint32_t dst, const void* src) {
    asm volatile("cp.async.cg.shared.global [%0], [%1], 16;" :: "r"(dst), "l"(src) : "memory");
}
#define CP_COMMIT() asm volatile("cp.async.commit_group;" ::: "memory")
#define CP_WAIT3()  asm volatile("cp.async.wait_group 3;" ::: "memory")
__device__ __forceinline__ void ldsm4(uint32_t r[4], uint32_t addr) {
    asm volatile("ldmatrix.sync.aligned.m8n8.x4.shared.b16 {%0,%1,%2,%3}, [%4];"
                 : "=r"(r[0]), "=r"(r[1]), "=r"(r[2]), "=r"(r[3]) : "r"(addr));
}
__device__ __forceinline__ void mma16816(float c[4], const uint32_t* a, const uint32_t* b) {
    asm volatile(
        "mma.sync.aligned.m16n8k16.row.col.f32.f16.f16.f32 "
        "{%0,%1,%2,%3}, {%4,%5,%6,%7}, {%8,%9}, {%0,%1,%2,%3};"
        : "+f"(c[0]), "+f"(c[1]), "+f"(c[2]), "+f"(c[3])
        : "r"(a[0]), "r"(a[1]), "r"(a[2]), "r"(a[3]), "r"(b[0]), "r"(b[1]));
}
__device__ __forceinline__ uint32_t h2u(half2 h) { return *reinterpret_cast<uint32_t*>(&h); }

// ---------------- small kernels ----------------------------------------------
__global__ void zero_out_kernel(float* out) {
    int i = blockIdx.x * blockDim.x + threadIdx.x;
    if (i < B_ * D_) out[i] = 0.0f;
}

// W1 [K][N] f32 -> W1T [N][K] f16 (transpose + convert)
__global__ void w1split_kernel(const float* __restrict__ W1) {
    __shared__ float t[32][33];
    const int n0 = blockIdx.x * 32, k0 = blockIdx.y * 32;
    const int tx = threadIdx.x, ty = threadIdx.y;  // (32, 8)
#pragma unroll
    for (int r = 0; r < 4; r++)
        t[ty + r * 8][tx] = W1[(size_t)(k0 + ty + r * 8) * U_ + n0 + tx];
    __syncthreads();
#pragma unroll
    for (int r = 0; r < 4; r++) {
        const float x = t[tx][ty + r * 8];
        g_w1t[(size_t)(n0 + ty + r * 8) * D_ + k0 + tx] = __float2half_rn(x);
    }
}

__global__ void hd_kernel(const float* __restrict__ dec,
                          const float* __restrict__ W2,
                          const float* __restrict__ b2) {
    __shared__ float ds[D_];
    int b = blockIdx.x;
    int u = threadIdx.x;
    ds[u] = dec[b * D_ + u];
    __syncthreads();
    float a = b2[u];
#pragma unroll 8
    for (int k = 0; k < D_; k++) a = fmaf(ds[k], W2[k * U_ + u], a);
    g_hd[b * U_ + u] = a;
}

// ---------------- prepass: enc f32 -> A fragments (f16) ----------------------
__global__ __launch_bounds__(256)
void encfrag_kernel(const float* __restrict__ enc) {
    __shared__ __align__(16) char sA[8][32 * 80];
    const int lane = threadIdx.x & 31, wid = threadIdx.x >> 5;
    const int mb = blockIdx.x * 8 + wid;
    const float* src = enc + (size_t)mb * 32 * D_;
    char* ws = sA[wid];
    const uint32_t base = smem_u32(ws);
    const uint32_t aoff = ((lane & 7) + ((lane >> 3) & 1) * 8) * 80 + ((lane >> 4) & 1) * 16;
    const int r0 = lane >> 3;        // 0..3
    const int c0 = (lane & 7) * 4;   // f32 col within k32 chunk

    for (int kt = 0; kt < 16; kt++) {
        const int k0 = kt * 32;
#pragma unroll
        for (int i = 0; i < 8; i++) {
            const int row = r0 + i * 4;
            float4 f = *(const float4*)(src + (size_t)row * D_ + k0 + c0);
            half2 h0 = __floats2half2_rn(f.x, f.y);
            half2 h1 = __floats2half2_rn(f.z, f.w);
            *(uint2*)(ws + row * 80 + c0 * 2) = make_uint2(h2u(h0), h2u(h1));
        }
        __syncwarp();
#pragma unroll
        for (int s = 0; s < 2; s++)
#pragma unroll
            for (int g = 0; g < 2; g++) {
                uint32_t r[4];
                ldsm4(r, base + g * 16 * 80 + s * 32 + aoff);
                g_encfrag[(((size_t)mb * 32 + kt * 2 + s) * 2 + g) * 32 + lane] =
                    make_uint4(r[0], r[1], r[2], r[3]);
            }
        __syncwarp();
    }
}

// ---------------- prepass: W1T f16 -> B fragments ----------------------------
__global__ void w1frag_kernel() {
    __shared__ __align__(16) char sB[64 * 80];
    const int lane = threadIdx.x;   // 32 threads
    const int nb = blockIdx.x;      // 0..7
    const uint32_t base = smem_u32(sB);
    const uint32_t boff = ((lane & 7) + ((lane >> 4) & 1) * 8) * 80 + ((lane >> 3) & 1) * 16;
    const int r0 = lane >> 3;       // 0..3
    const int c0 = (lane & 7) * 4;  // half col within k32 chunk

    for (int kt = 0; kt < 16; kt++) {
        const int k0 = kt * 32;
#pragma unroll
        for (int i = 0; i < 16; i++) {
            const int row = r0 + i * 4;   // 0..63
            uint2 v = *(const uint2*)(g_w1t + (size_t)(nb * 64 + row) * D_ + k0 + c0);
            *(uint2*)(sB + row * 80 + c0 * 2) = v;
        }
        __syncwarp();
#pragma unroll
        for (int s = 0; s < 2; s++)
#pragma unroll
            for (int g = 0; g < 4; g++) {
                uint32_t r[4];
                ldsm4(r, base + g * 16 * 80 + s * 32 + boff);
                g_w1frag[((nb * 32 + kt * 2 + s) * 4 + g) * 32 + lane] =
                    make_uint4(r[0], r[1], r[2], r[3]);
            }
        __syncwarp();
    }
}

// ---------------- main score kernel: cp.async 5-stage ring + HMMA ------------
// Stage layout (512 uint4 = 8KB): [0..255]  A frags: [mbLocal(4)][g(2)][lane(32)]
//                                 [256..511] B frags: [nbLocal(2)][g(4)][lane(32)]
__global__ __launch_bounds__(256, 2)
void score_pipe_kernel(const float* __restrict__ b1, const float* __restrict__ V) {
    __shared__ __align__(16) uint4 stg[STAGES][512];
    __shared__ float cpre[128], vpre[128], ssum[128];

    const int tid = threadIdx.x, lane = tid & 31, wid = tid >> 5;
    const int wm = wid >> 1, wn = wid & 1;
    const int n0 = blockIdx.x * 128, m0 = blockIdx.y * 128, b = m0 >> 11;

    if (tid < 128) {
        cpre[tid] = b1[n0 + tid] + g_hd[b * U_ + n0 + tid];
        vpre[tid] = V[n0 + tid];
        ssum[tid] = 0.0f;
    }

    // producer source pointers for this thread (advance by k per stage)
    const int mb0 = blockIdx.y * 4;
    const uint4* asrc = g_encfrag +
        (((size_t)(mb0 + (tid >> 6)) * 32) * 2 + ((tid >> 5) & 1)) * 32 + (tid & 31);
    const uint4* bsrc = g_w1frag +
        (((size_t)(blockIdx.x * 2 + (tid >> 7)) * 32) * 4 + ((tid >> 5) & 3)) * 32 + (tid & 31);
    // per-k16 strides: A +64 uint4, B +128 uint4

    // prologue: issue stages for k = 0..3
#pragma unroll
    for (int s = 0; s < 4; s++) {
        cp16(smem_u32(&stg[s][tid]), asrc + (size_t)s * 64);
        cp16(smem_u32(&stg[s][256 + tid]), bsrc + (size_t)s * 128);
        CP_COMMIT();
    }

    float acc[2][8][4] = {};
    // consumer smem pointers (within a stage)
    const int aoff = (wm * 2) * 32 + lane;           // +32 for g=1
    const int boff = 256 + (wn * 4) * 32 + lane;     // +32 per g

    int buf = 0, pbuf = 4;
    for (int k = 0; k < 32; k++) {
        CP_WAIT3();            // stage k complete
        __syncthreads();       // all warps done with stage k-1 reads; buffer reuse safe

        if (k + 4 < 32) {      // issue stage k+4 into pbuf
            cp16(smem_u32(&stg[pbuf][tid]), asrc + (size_t)(k + 4) * 64);
            cp16(smem_u32(&stg[pbuf][256 + tid]), bsrc + (size_t)(k + 4) * 128);
        }
        CP_COMMIT();           // commit (possibly empty) to keep group count in step

        const uint4* sa = &stg[buf][aoff];
        const uint4* sb = &stg[buf][boff];
        uint4 a0 = sa[0], a1 = sa[32];
        uint4 f0 = sb[0], f1 = sb[32], f2 = sb[64], f3 = sb[96];

        const uint32_t* A0 = (const uint32_t*)&a0;
        const uint32_t* A1 = (const uint32_t*)&a1;
        const uint32_t* B0 = (const uint32_t*)&f0;
        const uint32_t* B1 = (const uint32_t*)&f1;
        const uint32_t* B2 = (const uint32_t*)&f2;
        const uint32_t* B3 = (const uint32_t*)&f3;
        mma16816(acc[0][0], A0, B0); mma16816(acc[0][1], A0, B0 + 2);
        mma16816(acc[1][0], A1, B0); mma16816(acc[1][1], A1, B0 + 2);
        mma16816(acc[0][2], A0, B1); mma16816(acc[0][3], A0, B1 + 2);
        mma16816(acc[1][2], A1, B1); mma16816(acc[1][3], A1, B1 + 2);
        mma16816(acc[0][4], A0, B2); mma16816(acc[0][5], A0, B2 + 2);
        mma16816(acc[1][4], A1, B2); mma16816(acc[1][5], A1, B2 + 2);
        mma16816(acc[0][6], A0, B3); mma16816(acc[0][7], A0, B3 + 2);
        mma16816(acc[1][6], A1, B3); mma16816(acc[1][7], A1, B3 + 2);

        buf = (buf + 1 == STAGES) ? 0 : buf + 1;
        pbuf = (pbuf + 1 == STAGES) ? 0 : pbuf + 1;
    }

    __syncthreads();  // all MMAs done; cpre/vpre valid; ssum init visible

    // ---- epilogue: tanh + V-dot, reduce to row partials ----
    const int g = lane >> 2, tg = lane & 3;
    const int n_base = wn * 64;
    float p[2][2] = {{0.0f, 0.0f}, {0.0f, 0.0f}};
#pragma unroll
    for (int mf = 0; mf < 2; mf++) {
#pragma unroll
        for (int nf = 0; nf < 8; nf++) {
            const int c0 = n_base + nf * 8 + tg * 2;
            const float v0 = vpre[c0], v1 = vpre[c0 + 1];
            const float k0 = cpre[c0], k1 = cpre[c0 + 1];
            p[mf][0] += v0 * tanhf(acc[mf][nf][0] + k0) + v1 * tanhf(acc[mf][nf][1] + k1);
            p[mf][1] += v0 * tanhf(acc[mf][nf][2] + k0) + v1 * tanhf(acc[mf][nf][3] + k1);
        }
    }
#pragma unroll
    for (int mf = 0; mf < 2; mf++)
#pragma unroll
        for (int h = 0; h < 2; h++) {
            float s = p[mf][h];
            s += __shfl_xor_sync(0xffffffffu, s, 1);
            s += __shfl_xor_sync(0xffffffffu, s, 2);
            if (tg == 0) atomicAdd(&ssum[wm * 32 + mf * 16 + h * 8 + g], s);
        }
    __syncthreads();
    if (tid < 128) g_spart[(size_t)blockIdx.x * M_TOT + m0 + tid] = ssum[tid];
}

// ---------------- softmax stats (combines 4 partials) + context --------------
__global__ void stats_kernel() {
    const int b = blockIdx.x;
    const int tid = threadIdx.x;  // 256
    __shared__ float red[256];
    float m = -1e30f;
    for (int s = tid; s < S_; s += 256) {
        const int i = b * S_ + s;
        const float v = g_spart[i] + g_spart[M_TOT + i] + g_spart[2 * M_TOT + i] + g_spart[3 * M_TOT + i];
        g_scores[i] = v;
        m = fmaxf(m, v);
    }
    red[tid] = m;
    __syncthreads();
    for (int o = 128; o; o >>= 1) {
        if (tid < o) red[tid] = fmaxf(red[tid], red[tid + o]);
        __syncthreads();
    }
    const float mx = red[0];
    __syncthreads();
    float sum = 0.0f;
    for (int s = tid; s < S_; s += 256) sum += expf(g_scores[b * S_ + s] - mx);
    red[tid] = sum;
    __syncthreads();
    for (int o = 128; o; o >>= 1) {
        if (tid < o) red[tid] += red[tid + o];
        __syncthreads();
    }
    if (tid == 0) {
        g_max[b] = mx;
        g_invsum[b] = 1.0f / red[0];
    }
}

__global__ void context_kernel(const float* __restrict__ enc,
                               float* __restrict__ out) {
    __shared__ float attn[128];
    const int b = blockIdx.y;
    const int s0 = blockIdx.x * 128;
    const int tid = threadIdx.x;  // 256
    if (tid < 128)
        attn[tid] = expf(g_scores[b * S_ + s0 + tid] - g_max[b]) * g_invsum[b];
    __syncthreads();
    float acc0 = 0.0f, acc1 = 0.0f;
    const float* base = enc + ((size_t)b * S_ + s0) * D_;
#pragma unroll 4
    for (int s = 0; s < 128; s++) {
        const float w = attn[s];
        acc0 = fmaf(w, base[(size_t)s * D_ + tid], acc0);
        acc1 = fmaf(w, base[(size_t)s * D_ + tid + 256], acc1);
    }
    atomicAdd(&out[b * D_ + tid], acc0);
    atomicAdd(&out[b * D_ + tid + 256], acc1);
}

// ---------------- launch ------------------------------------------------------
extern "C" void kernel_launch(void* const* d_in, const int* in_sizes, int n_in,
                              void* d_out, int out_size) {
    const float* enc = (const float*)d_in[0];
    const float* dec = (const float*)d_in[1];
    const float* W1  = (const float*)d_in[2];
    const float* b1  = (const float*)d_in[3];
    const float* W2  = (const float*)d_in[4];
    const float* b2  = (const float*)d_in[5];
    const float* V   = (const float*)d_in[6];
    // d_in[7] = bv: constant shift, cancels in softmax.
    float* out = (float*)d_out;

    w1split_kernel<<<dim3(16, 16), dim3(32, 8)>>>(W1);
    w1frag_kernel<<<8, 32>>>();
    encfrag_kernel<<<MB_CNT / 8, 256>>>(enc);
    zero_out_kernel<<<(B_ * D_ + 255) / 256, 256>>>(out);
    hd_kernel<<<B_, U_>>>(dec, W2, b2);
    score_pipe_kernel<<<dim3(4, M_TOT / 128), 256>>>(b1, V);
    stats_kernel<<<B_, 256>>>();
    context_kernel<<<dim3(S_ / 128, B_), 256>>>(enc, out);
}

// round 8
// speedup vs baseline: 1.3272x; 1.0189x over previous
#include <cuda_runtime.h>
#include <cuda_fp16.h>
#include <cstdint>

#define B_ 64
#define S_ 2048
#define D_ 512
#define U_ 512
#define M_TOT (B_ * S_)
#define MB_CNT (M_TOT / 32)   // 4096 m32-blocks
#define STAGES 4              // k32 per stage, 16 stages total

// ---------------- scratch (__device__ globals: allocation-free rule) ----------
__device__ float g_hd[B_ * U_];
__device__ float g_scores[M_TOT];
__device__ float g_max[B_];
__device__ float g_invsum[B_];
__device__ float g_spart[4 * M_TOT];
__device__ __half g_w1t[U_ * D_];                  // [n][k] f16
__device__ uint4 g_encfrag[(size_t)MB_CNT * 2048]; // [mb][k16(32)][g(2)][lane(32)]
__device__ uint4 g_w1frag[8 * 4096];               // [nb][k16(32)][g(4)][lane(32)]

// ---------------- helpers ----------------------------------------------------
__device__ __forceinline__ uint32_t smem_u32(const void* p) {
    uint32_t a;
    asm("{ .reg .u64 t; cvta.to.shared.u64 t, %1; cvt.u32.u64 %0, t; }" : "=r"(a) : "l"(p));
    return a;
}
__device__ __forceinline__ void cp16(uint32_t dst, const void* src) {
    asm volatile("cp.async.cg.shared.global [%0], [%1], 16;" :: "r"(dst), "l"(src) : "memory");
}
#define CP_COMMIT() asm volatile("cp.async.commit_group;" ::: "memory")
#define CP_WAIT2()  asm volatile("cp.async.wait_group 2;" ::: "memory")
__device__ __forceinline__ void ldsm4(uint32_t r[4], uint32_t addr) {
    asm volatile("ldmatrix.sync.aligned.m8n8.x4.shared.b16 {%0,%1,%2,%3}, [%4];"
                 : "=r"(r[0]), "=r"(r[1]), "=r"(r[2]), "=r"(r[3]) : "r"(addr));
}
__device__ __forceinline__ void mma16816(float c[4], const uint32_t* a, const uint32_t* b) {
    asm volatile(
        "mma.sync.aligned.m16n8k16.row.col.f32.f16.f16.f32 "
        "{%0,%1,%2,%3}, {%4,%5,%6,%7}, {%8,%9}, {%0,%1,%2,%3};"
        : "+f"(c[0]), "+f"(c[1]), "+f"(c[2]), "+f"(c[3])
        : "r"(a[0]), "r"(a[1]), "r"(a[2]), "r"(a[3]), "r"(b[0]), "r"(b[1]));
}
__device__ __forceinline__ uint32_t h2u(half2 h) { return *reinterpret_cast<uint32_t*>(&h); }

// ---------------- small kernels ----------------------------------------------
__global__ void zero_out_kernel(float* out) {
    int i = blockIdx.x * blockDim.x + threadIdx.x;
    if (i < B_ * D_) out[i] = 0.0f;
}

// W1 [K][N] f32 -> W1T [N][K] f16 (transpose + convert)
__global__ void w1split_kernel(const float* __restrict__ W1) {
    __shared__ float t[32][33];
    const int n0 = blockIdx.x * 32, k0 = blockIdx.y * 32;
    const int tx = threadIdx.x, ty = threadIdx.y;  // (32, 8)
#pragma unroll
    for (int r = 0; r < 4; r++)
        t[ty + r * 8][tx] = W1[(size_t)(k0 + ty + r * 8) * U_ + n0 + tx];
    __syncthreads();
#pragma unroll
    for (int r = 0; r < 4; r++) {
        const float x = t[tx][ty + r * 8];
        g_w1t[(size_t)(n0 + ty + r * 8) * D_ + k0 + tx] = __float2half_rn(x);
    }
}

__global__ void hd_kernel(const float* __restrict__ dec,
                          const float* __restrict__ W2,
                          const float* __restrict__ b2) {
    __shared__ float ds[D_];
    int b = blockIdx.x;
    int u = threadIdx.x;
    ds[u] = dec[b * D_ + u];
    __syncthreads();
    float a = b2[u];
#pragma unroll 8
    for (int k = 0; k < D_; k++) a = fmaf(ds[k], W2[k * U_ + u], a);
    g_hd[b * U_ + u] = a;
}

// ---------------- prepass: enc f32 -> A fragments (f16) ----------------------
__global__ __launch_bounds__(256)
void encfrag_kernel(const float* __restrict__ enc) {
    __shared__ __align__(16) char sA[8][32 * 80];
    const int lane = threadIdx.x & 31, wid = threadIdx.x >> 5;
    const int mb = blockIdx.x * 8 + wid;
    const float* src = enc + (size_t)mb * 32 * D_;
    char* ws = sA[wid];
    const uint32_t base = smem_u32(ws);
    const uint32_t aoff = ((lane & 7) + ((lane >> 3) & 1) * 8) * 80 + ((lane >> 4) & 1) * 16;
    const int r0 = lane >> 3;        // 0..3
    const int c0 = (lane & 7) * 4;   // f32 col within k32 chunk

    for (int kt = 0; kt < 16; kt++) {
        const int k0 = kt * 32;
#pragma unroll
        for (int i = 0; i < 8; i++) {
            const int row = r0 + i * 4;
            float4 f = *(const float4*)(src + (size_t)row * D_ + k0 + c0);
            half2 h0 = __floats2half2_rn(f.x, f.y);
            half2 h1 = __floats2half2_rn(f.z, f.w);
            *(uint2*)(ws + row * 80 + c0 * 2) = make_uint2(h2u(h0), h2u(h1));
        }
        __syncwarp();
#pragma unroll
        for (int s = 0; s < 2; s++)
#pragma unroll
            for (int g = 0; g < 2; g++) {
                uint32_t r[4];
                ldsm4(r, base + g * 16 * 80 + s * 32 + aoff);
                g_encfrag[(((size_t)mb * 32 + kt * 2 + s) * 2 + g) * 32 + lane] =
                    make_uint4(r[0], r[1], r[2], r[3]);
            }
        __syncwarp();
    }
}

// ---------------- prepass: W1T f16 -> B fragments ----------------------------
__global__ void w1frag_kernel() {
    __shared__ __align__(16) char sB[64 * 80];
    const int lane = threadIdx.x;   // 32 threads
    const int nb = blockIdx.x;      // 0..7
    const uint32_t base = smem_u32(sB);
    const uint32_t boff = ((lane & 7) + ((lane >> 4) & 1) * 8) * 80 + ((lane >> 3) & 1) * 16;
    const int r0 = lane >> 3;       // 0..3
    const int c0 = (lane & 7) * 4;  // half col within k32 chunk

    for (int kt = 0; kt < 16; kt++) {
        const int k0 = kt * 32;
#pragma unroll
        for (int i = 0; i < 16; i++) {
            const int row = r0 + i * 4;   // 0..63
            uint2 v = *(const uint2*)(g_w1t + (size_t)(nb * 64 + row) * D_ + k0 + c0);
            *(uint2*)(sB + row * 80 + c0 * 2) = v;
        }
        __syncwarp();
#pragma unroll
        for (int s = 0; s < 2; s++)
#pragma unroll
            for (int g = 0; g < 4; g++) {
                uint32_t r[4];
                ldsm4(r, base + g * 16 * 80 + s * 32 + boff);
                g_w1frag[((nb * 32 + kt * 2 + s) * 4 + g) * 32 + lane] =
                    make_uint4(r[0], r[1], r[2], r[3]);
            }
        __syncwarp();
    }
}

// ---------------- main score kernel: cp.async k32 stages + HMMA --------------
// Stage = 1024 uint4 (16KB): two k16 halves; each half: A frags [0..255], B frags [256..511].
#define STG_U4 1024
#define SMEM_STG_BYTES (STAGES * STG_U4 * 16)  // 65536
#define SMEM_DYN_TOTAL (SMEM_STG_BYTES + 3 * 128 * 4)

__global__ __launch_bounds__(256, 2)
void score_pipe_kernel(const float* __restrict__ b1, const float* __restrict__ V) {
    extern __shared__ __align__(16) char smem[];
    uint4* stg = (uint4*)smem;
    float* cpre = (float*)(smem + SMEM_STG_BYTES);
    float* vpre = cpre + 128;
    float* ssum = vpre + 128;

    const int tid = threadIdx.x, lane = tid & 31, wid = tid >> 5;
    const int wm = wid >> 1, wn = wid & 1;
    const int n0 = blockIdx.x * 128, m0 = blockIdx.y * 128, b = m0 >> 11;

    if (tid < 128) {
        cpre[tid] = b1[n0 + tid] + g_hd[b * U_ + n0 + tid];
        vpre[tid] = V[n0 + tid];
        ssum[tid] = 0.0f;
    }

    // producer source pointers (per thread); per-k16 strides: A +64, B +128 uint4
    const int mb0 = blockIdx.y * 4;
    const uint4* asrc = g_encfrag +
        (((size_t)(mb0 + (tid >> 6)) * 32) * 2 + ((tid >> 5) & 1)) * 32 + (tid & 31);
    const uint4* bsrc = g_w1frag +
        (((size_t)(blockIdx.x * 2 + (tid >> 7)) * 32) * 4 + ((tid >> 5) & 3)) * 32 + (tid & 31);

    // prologue: issue stages 0..2 (k32 each)
#pragma unroll
    for (int s = 0; s < 3; s++) {
        uint4* sp = stg + s * STG_U4;
        cp16(smem_u32(sp + tid),        asrc + (size_t)(2 * s) * 64);
        cp16(smem_u32(sp + 256 + tid),  bsrc + (size_t)(2 * s) * 128);
        cp16(smem_u32(sp + 512 + tid),  asrc + (size_t)(2 * s + 1) * 64);
        cp16(smem_u32(sp + 768 + tid),  bsrc + (size_t)(2 * s + 1) * 128);
        CP_COMMIT();
    }

    float acc[2][8][4] = {};
    const int aoff = (wm * 2) * 32 + lane;          // +32 for g=1
    const int boff = 256 + (wn * 4) * 32 + lane;    // +32 per g

    int buf = 0, pbuf = 3;
    for (int st = 0; st < 16; st++) {
        CP_WAIT2();            // stage st complete
        __syncthreads();       // all warps done reading stage st-1's old contents

        if (st + 3 < 16) {     // issue stage st+3
            uint4* sp = stg + pbuf * STG_U4;
            cp16(smem_u32(sp + tid),        asrc + (size_t)(2 * (st + 3)) * 64);
            cp16(smem_u32(sp + 256 + tid),  bsrc + (size_t)(2 * (st + 3)) * 128);
            cp16(smem_u32(sp + 512 + tid),  asrc + (size_t)(2 * (st + 3) + 1) * 64);
            cp16(smem_u32(sp + 768 + tid),  bsrc + (size_t)(2 * (st + 3) + 1) * 128);
        }
        CP_COMMIT();           // keep group accounting in lockstep

        const uint4* base = stg + buf * STG_U4;
#pragma unroll
        for (int sub = 0; sub < 2; sub++) {
            const uint4* sa = base + sub * 512 + aoff;
            const uint4* sb = base + sub * 512 + boff;
            uint4 a0 = sa[0], a1 = sa[32];
            uint4 f0 = sb[0], f1 = sb[32], f2 = sb[64], f3 = sb[96];
            const uint32_t* A0 = (const uint32_t*)&a0;
            const uint32_t* A1 = (const uint32_t*)&a1;
            const uint32_t* B0 = (const uint32_t*)&f0;
            const uint32_t* B1 = (const uint32_t*)&f1;
            const uint32_t* B2 = (const uint32_t*)&f2;
            const uint32_t* B3 = (const uint32_t*)&f3;
            mma16816(acc[0][0], A0, B0); mma16816(acc[0][1], A0, B0 + 2);
            mma16816(acc[1][0], A1, B0); mma16816(acc[1][1], A1, B0 + 2);
            mma16816(acc[0][2], A0, B1); mma16816(acc[0][3], A0, B1 + 2);
            mma16816(acc[1][2], A1, B1); mma16816(acc[1][3], A1, B1 + 2);
            mma16816(acc[0][4], A0, B2); mma16816(acc[0][5], A0, B2 + 2);
            mma16816(acc[1][4], A1, B2); mma16816(acc[1][5], A1, B2 + 2);
            mma16816(acc[0][6], A0, B3); mma16816(acc[0][7], A0, B3 + 2);
            mma16816(acc[1][6], A1, B3); mma16816(acc[1][7], A1, B3 + 2);
        }

        buf = (buf + 1 == STAGES) ? 0 : buf + 1;
        pbuf = (pbuf + 1 == STAGES) ? 0 : pbuf + 1;
    }

    __syncthreads();  // all MMAs done; cpre/vpre/ssum valid

    // ---- epilogue: tanh + V-dot, reduce to row partials ----
    const int g = lane >> 2, tg = lane & 3;
    const int n_base = wn * 64;
    float p[2][2] = {{0.0f, 0.0f}, {0.0f, 0.0f}};
#pragma unroll
    for (int mf = 0; mf < 2; mf++) {
#pragma unroll
        for (int nf = 0; nf < 8; nf++) {
            const int c0 = n_base + nf * 8 + tg * 2;
            const float v0 = vpre[c0], v1 = vpre[c0 + 1];
            const float k0 = cpre[c0], k1 = cpre[c0 + 1];
            p[mf][0] += v0 * tanhf(acc[mf][nf][0] + k0) + v1 * tanhf(acc[mf][nf][1] + k1);
            p[mf][1] += v0 * tanhf(acc[mf][nf][2] + k0) + v1 * tanhf(acc[mf][nf][3] + k1);
        }
    }
#pragma unroll
    for (int mf = 0; mf < 2; mf++)
#pragma unroll
        for (int h = 0; h < 2; h++) {
            float s = p[mf][h];
            s += __shfl_xor_sync(0xffffffffu, s, 1);
            s += __shfl_xor_sync(0xffffffffu, s, 2);
            if (tg == 0) atomicAdd(&ssum[wm * 32 + mf * 16 + h * 8 + g], s);
        }
    __syncthreads();
    if (tid < 128) g_spart[(size_t)blockIdx.x * M_TOT + m0 + tid] = ssum[tid];
}

// ---------------- softmax stats (combines 4 partials) + context --------------
__global__ void stats_kernel() {
    const int b = blockIdx.x;
    const int tid = threadIdx.x;  // 256
    __shared__ float red[256];
    float m = -1e30f;
    for (int s = tid; s < S_; s += 256) {
        const int i = b * S_ + s;
        const float v = g_spart[i] + g_spart[M_TOT + i] + g_spart[2 * M_TOT + i] + g_spart[3 * M_TOT + i];
        g_scores[i] = v;
        m = fmaxf(m, v);
    }
    red[tid] = m;
    __syncthreads();
    for (int o = 128; o; o >>= 1) {
        if (tid < o) red[tid] = fmaxf(red[tid], red[tid + o]);
        __syncthreads();
    }
    const float mx = red[0];
    __syncthreads();
    float sum = 0.0f;
    for (int s = tid; s < S_; s += 256) sum += expf(g_scores[b * S_ + s] - mx);
    red[tid] = sum;
    __syncthreads();
    for (int o = 128; o; o >>= 1) {
        if (tid < o) red[tid] += red[tid + o];
        __syncthreads();
    }
    if (tid == 0) {
        g_max[b] = mx;
        g_invsum[b] = 1.0f / red[0];
    }
}

__global__ void context_kernel(const float* __restrict__ enc,
                               float* __restrict__ out) {
    __shared__ float attn[128];
    const int b = blockIdx.y;
    const int s0 = blockIdx.x * 128;
    const int tid = threadIdx.x;  // 256
    if (tid < 128)
        attn[tid] = expf(g_scores[b * S_ + s0 + tid] - g_max[b]) * g_invsum[b];
    __syncthreads();
    float acc0 = 0.0f, acc1 = 0.0f;
    const float* base = enc + ((size_t)b * S_ + s0) * D_;
#pragma unroll 4
    for (int s = 0; s < 128; s++) {
        const float w = attn[s];
        acc0 = fmaf(w, base[(size_t)s * D_ + tid], acc0);
        acc1 = fmaf(w, base[(size_t)s * D_ + tid + 256], acc1);
    }
    atomicAdd(&out[b * D_ + tid], acc0);
    atomicAdd(&out[b * D_ + tid + 256], acc1);
}

// ---------------- launch ------------------------------------------------------
extern "C" void kernel_launch(void* const* d_in, const int* in_sizes, int n_in,
                              void* d_out, int out_size) {
    const float* enc = (const float*)d_in[0];
    const float* dec = (const float*)d_in[1];
    const float* W1  = (const float*)d_in[2];
    const float* b1  = (const float*)d_in[3];
    const float* W2  = (const float*)d_in[4];
    const float* b2  = (const float*)d_in[5];
    const float* V   = (const float*)d_in[6];
    // d_in[7] = bv: constant shift, cancels in softmax.
    float* out = (float*)d_out;

    cudaFuncSetAttribute(score_pipe_kernel,
                         cudaFuncAttributeMaxDynamicSharedMemorySize, SMEM_DYN_TOTAL);

    w1split_kernel<<<dim3(16, 16), dim3(32, 8)>>>(W1);
    w1frag_kernel<<<8, 32>>>();
    encfrag_kernel<<<MB_CNT / 8, 256>>>(enc);
    zero_out_kernel<<<(B_ * D_ + 255) / 256, 256>>>(out);
    hd_kernel<<<B_, U_>>>(dec, W2, b2);
    score_pipe_kernel<<<dim3(4, M_TOT / 128), 256, SMEM_DYN_TOTAL>>>(b1, V);
    stats_kernel<<<B_, 256>>>();
    context_kernel<<<dim3(S_ / 128, B_), 256>>>(enc, out);
}

// round 9
// speedup vs baseline: 1.3314x; 1.0032x over previous
#include <cuda_runtime.h>
#include <cuda_fp16.h>
#include <cstdint>

#define B_ 64
#define S_ 2048
#define D_ 512
#define U_ 512
#define M_TOT (B_ * S_)
#define MB_CNT (M_TOT / 32)   // 4096 m32-blocks
#define STAGES 4              // k32 per stage (B only), 16 stages total

// ---------------- scratch (__device__ globals: allocation-free rule) ----------
__device__ float g_hd[B_ * U_];
__device__ float g_scores[M_TOT];
__device__ float g_max[B_];
__device__ float g_invsum[B_];
__device__ float g_spart[4 * M_TOT];
__device__ __half g_w1t[U_ * D_];                  // [n][k] f16
__device__ uint4 g_encfrag[(size_t)MB_CNT * 2048]; // [mb][k16(32)][g(2)][lane(32)]
__device__ uint4 g_w1frag[8 * 4096];               // [nb][k16(32)][g(4)][lane(32)]

// ---------------- helpers ----------------------------------------------------
__device__ __forceinline__ uint32_t smem_u32(const void* p) {
    uint32_t a;
    asm("{ .reg .u64 t; cvta.to.shared.u64 t, %1; cvt.u32.u64 %0, t; }" : "=r"(a) : "l"(p));
    return a;
}
__device__ __forceinline__ void cp16(uint32_t dst, const void* src) {
    asm volatile("cp.async.cg.shared.global [%0], [%1], 16;" :: "r"(dst), "l"(src) : "memory");
}
#define CP_COMMIT() asm volatile("cp.async.commit_group;" ::: "memory")
#define CP_WAIT2()  asm volatile("cp.async.wait_group 2;" ::: "memory")
__device__ __forceinline__ void ldsm4(uint32_t r[4], uint32_t addr) {
    asm volatile("ldmatrix.sync.aligned.m8n8.x4.shared.b16 {%0,%1,%2,%3}, [%4];"
                 : "=r"(r[0]), "=r"(r[1]), "=r"(r[2]), "=r"(r[3]) : "r"(addr));
}
__device__ __forceinline__ void mma16816(float c[4], const uint32_t* a, const uint32_t* b) {
    asm volatile(
        "mma.sync.aligned.m16n8k16.row.col.f32.f16.f16.f32 "
        "{%0,%1,%2,%3}, {%4,%5,%6,%7}, {%8,%9}, {%0,%1,%2,%3};"
        : "+f"(c[0]), "+f"(c[1]), "+f"(c[2]), "+f"(c[3])
        : "r"(a[0]), "r"(a[1]), "r"(a[2]), "r"(a[3]), "r"(b[0]), "r"(b[1]));
}
__device__ __forceinline__ uint32_t h2u(half2 h) { return *reinterpret_cast<uint32_t*>(&h); }

// ---------------- small kernels ----------------------------------------------
__global__ void zero_out_kernel(float* out) {
    int i = blockIdx.x * blockDim.x + threadIdx.x;
    if (i < B_ * D_) out[i] = 0.0f;
}

// W1 [K][N] f32 -> W1T [N][K] f16 (transpose + convert)
__global__ void w1split_kernel(const float* __restrict__ W1) {
    __shared__ float t[32][33];
    const int n0 = blockIdx.x * 32, k0 = blockIdx.y * 32;
    const int tx = threadIdx.x, ty = threadIdx.y;  // (32, 8)
#pragma unroll
    for (int r = 0; r < 4; r++)
        t[ty + r * 8][tx] = W1[(size_t)(k0 + ty + r * 8) * U_ + n0 + tx];
    __syncthreads();
#pragma unroll
    for (int r = 0; r < 4; r++) {
        const float x = t[tx][ty + r * 8];
        g_w1t[(size_t)(n0 + ty + r * 8) * D_ + k0 + tx] = __float2half_rn(x);
    }
}

__global__ void hd_kernel(const float* __restrict__ dec,
                          const float* __restrict__ W2,
                          const float* __restrict__ b2) {
    __shared__ float ds[D_];
    int b = blockIdx.x;
    int u = threadIdx.x;
    ds[u] = dec[b * D_ + u];
    __syncthreads();
    float a = b2[u];
#pragma unroll 8
    for (int k = 0; k < D_; k++) a = fmaf(ds[k], W2[k * U_ + u], a);
    g_hd[b * U_ + u] = a;
}

// ---------------- prepass: enc f32 -> A fragments (f16) ----------------------
__global__ __launch_bounds__(256)
void encfrag_kernel(const float* __restrict__ enc) {
    __shared__ __align__(16) char sA[8][32 * 80];
    const int lane = threadIdx.x & 31, wid = threadIdx.x >> 5;
    const int mb = blockIdx.x * 8 + wid;
    const float* src = enc + (size_t)mb * 32 * D_;
    char* ws = sA[wid];
    const uint32_t base = smem_u32(ws);
    const uint32_t aoff = ((lane & 7) + ((lane >> 3) & 1) * 8) * 80 + ((lane >> 4) & 1) * 16;
    const int r0 = lane >> 3;        // 0..3
    const int c0 = (lane & 7) * 4;   // f32 col within k32 chunk

    for (int kt = 0; kt < 16; kt++) {
        const int k0 = kt * 32;
#pragma unroll
        for (int i = 0; i < 8; i++) {
            const int row = r0 + i * 4;
            float4 f = *(const float4*)(src + (size_t)row * D_ + k0 + c0);
            half2 h0 = __floats2half2_rn(f.x, f.y);
            half2 h1 = __floats2half2_rn(f.z, f.w);
            *(uint2*)(ws + row * 80 + c0 * 2) = make_uint2(h2u(h0), h2u(h1));
        }
        __syncwarp();
#pragma unroll
        for (int s = 0; s < 2; s++)
#pragma unroll
            for (int g = 0; g < 2; g++) {
                uint32_t r[4];
                ldsm4(r, base + g * 16 * 80 + s * 32 + aoff);
                g_encfrag[(((size_t)mb * 32 + kt * 2 + s) * 2 + g) * 32 + lane] =
                    make_uint4(r[0], r[1], r[2], r[3]);
            }
        __syncwarp();
    }
}

// ---------------- prepass: W1T f16 -> B fragments ----------------------------
__global__ void w1frag_kernel() {
    __shared__ __align__(16) char sB[64 * 80];
    const int lane = threadIdx.x;   // 32 threads
    const int nb = blockIdx.x;      // 0..7
    const uint32_t base = smem_u32(sB);
    const uint32_t boff = ((lane & 7) + ((lane >> 4) & 1) * 8) * 80 + ((lane >> 3) & 1) * 16;
    const int r0 = lane >> 3;       // 0..3
    const int c0 = (lane & 7) * 4;  // half col within k32 chunk

    for (int kt = 0; kt < 16; kt++) {
        const int k0 = kt * 32;
#pragma unroll
        for (int i = 0; i < 16; i++) {
            const int row = r0 + i * 4;   // 0..63
            uint2 v = *(const uint2*)(g_w1t + (size_t)(nb * 64 + row) * D_ + k0 + c0);
            *(uint2*)(sB + row * 80 + c0 * 2) = v;
        }
        __syncwarp();
#pragma unroll
        for (int s = 0; s < 2; s++)
#pragma unroll
            for (int g = 0; g < 4; g++) {
                uint32_t r[4];
                ldsm4(r, base + g * 16 * 80 + s * 32 + boff);
                g_w1frag[((nb * 32 + kt * 2 + s) * 4 + g) * 32 + lane] =
                    make_uint4(r[0], r[1], r[2], r[3]);
            }
        __syncwarp();
    }
}

// ---------------- main score kernel: B smem ring, A direct LDG ---------------
// B stage = 512 uint4 (8KB): [sub(2)][nbLocal(2)][g(4)][lane(32)]
#define STG_U4 512
#define SMEM_STG_BYTES (STAGES * STG_U4 * 16)  // 32768
#define SMEM_DYN_TOTAL (SMEM_STG_BYTES + 3 * 128 * 4)

__global__ __launch_bounds__(256, 2)
void score_pipe_kernel(const float* __restrict__ b1, const float* __restrict__ V) {
    extern __shared__ __align__(16) char smem[];
    uint4* stg = (uint4*)smem;
    float* cpre = (float*)(smem + SMEM_STG_BYTES);
    float* vpre = cpre + 128;
    float* ssum = vpre + 128;

    const int tid = threadIdx.x, lane = tid & 31, wid = tid >> 5;
    const int wm = wid >> 1, wn = wid & 1;
    const int n0 = blockIdx.x * 128, m0 = blockIdx.y * 128, b = m0 >> 11;

    if (tid < 128) {
        cpre[tid] = b1[n0 + tid] + g_hd[b * U_ + n0 + tid];
        vpre[tid] = V[n0 + tid];
        ssum[tid] = 0.0f;
    }

    // B producer pointer (per thread); per-k16 stride = 128 uint4
    const uint4* bsrc = g_w1frag +
        (((size_t)(blockIdx.x * 2 + (tid >> 7)) * 32) * 4 + ((tid >> 5) & 3)) * 32 + (tid & 31);

    // A consumer pointer (per warp, direct LDG); per-k16 stride = 64 uint4
    const uint4* Ap = g_encfrag + (size_t)(blockIdx.y * 4 + wm) * 2048 + lane;

    // prologue: issue B stages 0..2 (k32 each)
#pragma unroll
    for (int s = 0; s < 3; s++) {
        uint4* sp = stg + s * STG_U4;
        cp16(smem_u32(sp + tid),       bsrc + (size_t)(2 * s) * 128);
        cp16(smem_u32(sp + 256 + tid), bsrc + (size_t)(2 * s + 1) * 128);
        CP_COMMIT();
    }

    // prologue A regs: stage 0 (k16 = 0 and 1)
    uint4 a00 = Ap[0],  a01 = Ap[32];    // sub0: g0, g1
    uint4 a10 = Ap[64], a11 = Ap[96];    // sub1: g0, g1

    float acc[2][8][4] = {};
    const int boff = wn * 128 + lane;    // + g*32 within sub region

    int buf = 0, pbuf = 3;
#pragma unroll 4
    for (int st = 0; st < 16; st++) {
        CP_WAIT2();            // B stage st complete
        __syncthreads();       // all warps done reading pbuf's old contents

        if (st + 3 < 16) {     // issue B stage st+3
            uint4* sp = stg + pbuf * STG_U4;
            cp16(smem_u32(sp + tid),       bsrc + (size_t)(2 * (st + 3)) * 128);
            cp16(smem_u32(sp + 256 + tid), bsrc + (size_t)(2 * (st + 3) + 1) * 128);
        }
        CP_COMMIT();

        const uint4* sb = stg + buf * STG_U4;

        // ---- sub 0 ----
        {
            uint4 f0 = sb[boff], f1 = sb[boff + 32], f2 = sb[boff + 64], f3 = sb[boff + 96];
            const uint32_t* A0 = (const uint32_t*)&a00;
            const uint32_t* A1 = (const uint32_t*)&a01;
            const uint32_t* B0 = (const uint32_t*)&f0;
            const uint32_t* B1 = (const uint32_t*)&f1;
            const uint32_t* B2 = (const uint32_t*)&f2;
            const uint32_t* B3 = (const uint32_t*)&f3;
            mma16816(acc[0][0], A0, B0); mma16816(acc[0][1], A0, B0 + 2);
            mma16816(acc[1][0], A1, B0); mma16816(acc[1][1], A1, B0 + 2);
            mma16816(acc[0][2], A0, B1); mma16816(acc[0][3], A0, B1 + 2);
            mma16816(acc[1][2], A1, B1); mma16816(acc[1][3], A1, B1 + 2);
            mma16816(acc[0][4], A0, B2); mma16816(acc[0][5], A0, B2 + 2);
            mma16816(acc[1][4], A1, B2); mma16816(acc[1][5], A1, B2 + 2);
            mma16816(acc[0][6], A0, B3); mma16816(acc[0][7], A0, B3 + 2);
            mma16816(acc[1][6], A1, B3); mma16816(acc[1][7], A1, B3 + 2);
        }
        if (st < 15) {  // reload sub0 A regs for next stage (WAR after MMA issue)
            a00 = Ap[(size_t)(2 * st + 2) * 64];
            a01 = Ap[(size_t)(2 * st + 2) * 64 + 32];
        }

        // ---- sub 1 ----
        {
            const uint4* sb1 = sb + 256;
            uint4 f0 = sb1[boff], f1 = sb1[boff + 32], f2 = sb1[boff + 64], f3 = sb1[boff + 96];
            const uint32_t* A0 = (const uint32_t*)&a10;
            const uint32_t* A1 = (const uint32_t*)&a11;
            const uint32_t* B0 = (const uint32_t*)&f0;
            const uint32_t* B1 = (const uint32_t*)&f1;
            const uint32_t* B2 = (const uint32_t*)&f2;
            const uint32_t* B3 = (const uint32_t*)&f3;
            mma16816(acc[0][0], A0, B0); mma16816(acc[0][1], A0, B0 + 2);
            mma16816(acc[1][0], A1, B0); mma16816(acc[1][1], A1, B0 + 2);
            mma16816(acc[0][2], A0, B1); mma16816(acc[0][3], A0, B1 + 2);
            mma16816(acc[1][2], A1, B1); mma16816(acc[1][3], A1, B1 + 2);
            mma16816(acc[0][4], A0, B2); mma16816(acc[0][5], A0, B2 + 2);
            mma16816(acc[1][4], A1, B2); mma16816(acc[1][5], A1, B2 + 2);
            mma16816(acc[0][6], A0, B3); mma16816(acc[0][7], A0, B3 + 2);
            mma16816(acc[1][6], A1, B3); mma16816(acc[1][7], A1, B3 + 2);
        }
        if (st < 15) {  // reload sub1 A regs for next stage
            a10 = Ap[(size_t)(2 * st + 3) * 64];
            a11 = Ap[(size_t)(2 * st + 3) * 64 + 32];
        }

        buf = (buf + 1) & 3;
        pbuf = (pbuf + 1) & 3;
    }

    __syncthreads();  // all MMAs done; cpre/vpre/ssum valid

    // ---- epilogue: tanh + V-dot, reduce to row partials ----
    const int g = lane >> 2, tg = lane & 3;
    const int n_base = wn * 64;
    float p[2][2] = {{0.0f, 0.0f}, {0.0f, 0.0f}};
#pragma unroll
    for (int mf = 0; mf < 2; mf++) {
#pragma unroll
        for (int nf = 0; nf < 8; nf++) {
            const int c0 = n_base + nf * 8 + tg * 2;
            const float v0 = vpre[c0], v1 = vpre[c0 + 1];
            const float k0 = cpre[c0], k1 = cpre[c0 + 1];
            p[mf][0] += v0 * tanhf(acc[mf][nf][0] + k0) + v1 * tanhf(acc[mf][nf][1] + k1);
            p[mf][1] += v0 * tanhf(acc[mf][nf][2] + k0) + v1 * tanhf(acc[mf][nf][3] + k1);
        }
    }
#pragma unroll
    for (int mf = 0; mf < 2; mf++)
#pragma unroll
        for (int h = 0; h < 2; h++) {
            float s = p[mf][h];
            s += __shfl_xor_sync(0xffffffffu, s, 1);
            s += __shfl_xor_sync(0xffffffffu, s, 2);
            if (tg == 0) atomicAdd(&ssum[wm * 32 + mf * 16 + h * 8 + g], s);
        }
    __syncthreads();
    if (tid < 128) g_spart[(size_t)blockIdx.x * M_TOT + m0 + tid] = ssum[tid];
}

// ---------------- softmax stats (combines 4 partials) + context --------------
__global__ void stats_kernel() {
    const int b = blockIdx.x;
    const int tid = threadIdx.x;  // 256
    __shared__ float red[256];
    float m = -1e30f;
    for (int s = tid; s < S_; s += 256) {
        const int i = b * S_ + s;
        const float v = g_spart[i] + g_spart[M_TOT + i] + g_spart[2 * M_TOT + i] + g_spart[3 * M_TOT + i];
        g_scores[i] = v;
        m = fmaxf(m, v);
    }
    red[tid] = m;
    __syncthreads();
    for (int o = 128; o; o >>= 1) {
        if (tid < o) red[tid] = fmaxf(red[tid], red[tid + o]);
        __syncthreads();
    }
    const float mx = red[0];
    __syncthreads();
    float sum = 0.0f;
    for (int s = tid; s < S_; s += 256) sum += expf(g_scores[b * S_ + s] - mx);
    red[tid] = sum;
    __syncthreads();
    for (int o = 128; o; o >>= 1) {
        if (tid < o) red[tid] += red[tid + o];
        __syncthreads();
    }
    if (tid == 0) {
        g_max[b] = mx;
        g_invsum[b] = 1.0f / red[0];
    }
}

// context: 128 threads, each owns one float4 column; rows read fully coalesced.
__global__ void context_kernel(const float* __restrict__ enc,
                               float* __restrict__ out) {
    __shared__ float attn[128];
    const int b = blockIdx.y;
    const int s0 = blockIdx.x * 128;
    const int tid = threadIdx.x;  // 128
    attn[tid] = expf(g_scores[b * S_ + s0 + tid] - g_max[b]) * g_invsum[b];
    __syncthreads();
    const float4* base = (const float4*)(enc + ((size_t)b * S_ + s0) * D_);
    float ax = 0.0f, ay = 0.0f, az = 0.0f, aw = 0.0f;
#pragma unroll 4
    for (int s = 0; s < 128; s++) {
        const float w = attn[s];
        const float4 v = base[(size_t)s * 128 + tid];
        ax = fmaf(w, v.x, ax);
        ay = fmaf(w, v.y, ay);
        az = fmaf(w, v.z, az);
        aw = fmaf(w, v.w, aw);
    }
    float* o = out + b * D_ + tid * 4;
    atomicAdd(o + 0, ax);
    atomicAdd(o + 1, ay);
    atomicAdd(o + 2, az);
    atomicAdd(o + 3, aw);
}

// ---------------- launch ------------------------------------------------------
extern "C" void kernel_launch(void* const* d_in, const int* in_sizes, int n_in,
                              void* d_out, int out_size) {
    const float* enc = (const float*)d_in[0];
    const float* dec = (const float*)d_in[1];
    const float* W1  = (const float*)d_in[2];
    const float* b1  = (const float*)d_in[3];
    const float* W2  = (const float*)d_in[4];
    const float* b2  = (const float*)d_in[5];
    const float* V   = (const float*)d_in[6];
    // d_in[7] = bv: constant shift, cancels in softmax.
    float* out = (float*)d_out;

    cudaFuncSetAttribute(score_pipe_kernel,
                         cudaFuncAttributeMaxDynamicSharedMemorySize, SMEM_DYN_TOTAL);

    w1split_kernel<<<dim3(16, 16), dim3(32, 8)>>>(W1);
    w1frag_kernel<<<8, 32>>>();
    encfrag_kernel<<<MB_CNT / 8, 256>>>(enc);
    zero_out_kernel<<<(B_ * D_ + 255) / 256, 256>>>(out);
    hd_kernel<<<B_, U_>>>(dec, W2, b2);
    score_pipe_kernel<<<dim3(4, M_TOT / 128), 256, SMEM_DYN_TOTAL>>>(b1, V);
    stats_kernel<<<B_, 256>>>();
    context_kernel<<<dim3(S_ / 128, B_), 128>>>(enc, out);
}

// round 10
// speedup vs baseline: 1.3580x; 1.0200x over previous
#include <cuda_runtime.h>
#include <cuda_fp16.h>
#include <cstdint>

#define B_ 64
#define S_ 2048
#define D_ 512
#define U_ 512
#define M_TOT (B_ * S_)
#define MB_CNT (M_TOT / 32)   // 4096 m32-blocks
#define STAGES 4              // k32 per stage (B ring), 16 stages total
#define NCHUNK 16             // context s-chunks

// ---------------- scratch (__device__ globals: allocation-free rule) ----------
__device__ float g_hd[B_ * U_];
__device__ float g_scores[M_TOT];
__device__ float g_max[B_];
__device__ float g_invsum[B_];
__device__ float g_spart[4 * M_TOT];
__device__ float g_ctx[NCHUNK * B_ * D_];          // context partials [chunk][b][d]
__device__ uint4 g_encfrag[(size_t)MB_CNT * 2048]; // [mb][k16(32)][g(2)][lane(32)]
__device__ uint4 g_w1frag[8 * 4096];               // [nb][k16(32)][g(4)][lane(32)]

// ---------------- helpers ----------------------------------------------------
__device__ __forceinline__ uint32_t smem_u32(const void* p) {
    uint32_t a;
    asm("{ .reg .u64 t; cvta.to.shared.u64 t, %1; cvt.u32.u64 %0, t; }" : "=r"(a) : "l"(p));
    return a;
}
__device__ __forceinline__ void cp16(uint32_t dst, const void* src) {
    asm volatile("cp.async.cg.shared.global [%0], [%1], 16;" :: "r"(dst), "l"(src) : "memory");
}
#define CP_COMMIT() asm volatile("cp.async.commit_group;" ::: "memory")
#define CP_WAIT2()  asm volatile("cp.async.wait_group 2;" ::: "memory")
__device__ __forceinline__ void ldsm4(uint32_t r[4], uint32_t addr) {
    asm volatile("ldmatrix.sync.aligned.m8n8.x4.shared.b16 {%0,%1,%2,%3}, [%4];"
                 : "=r"(r[0]), "=r"(r[1]), "=r"(r[2]), "=r"(r[3]) : "r"(addr));
}
__device__ __forceinline__ void mma16816(float c[4], const uint32_t* a, const uint32_t* b) {
    asm volatile(
        "mma.sync.aligned.m16n8k16.row.col.f32.f16.f16.f32 "
        "{%0,%1,%2,%3}, {%4,%5,%6,%7}, {%8,%9}, {%0,%1,%2,%3};"
        : "+f"(c[0]), "+f"(c[1]), "+f"(c[2]), "+f"(c[3])
        : "r"(a[0]), "r"(a[1]), "r"(a[2]), "r"(a[3]), "r"(b[0]), "r"(b[1]));
}
__device__ __forceinline__ uint32_t h2u(half2 h) { return *reinterpret_cast<uint32_t*>(&h); }

// ---------------- merged W1 prepass: transpose + f16 + fragment extract ------
// One CTA per nb (64 n-rows). smem: [64 n][520 k] f16 (row stride 1040B, 16B-aligned).
#define WT_STRIDE 520
#define WT_SMEM (64 * WT_STRIDE * 2)

__global__ __launch_bounds__(256)
void wfrag_kernel(const float* __restrict__ W1) {
    extern __shared__ __align__(16) char smem[];
    __half* swt = (__half*)smem;
    const int tid = threadIdx.x, lane = tid & 31, wid = tid >> 5;
    const int nb = blockIdx.x;                 // 0..7
    const int nl = tid & 63, kg = tid >> 6;    // 64 n-cols x 4 k-groups

    // transpose-load W1[k][n] -> swt[n][k], f32 -> f16
    for (int i = 0; i < 128; i++) {
        const int k = kg * 128 + i;
        swt[nl * WT_STRIDE + k] = __float2half_rn(W1[(size_t)k * U_ + nb * 64 + nl]);
    }
    __syncthreads();

    // fragment extraction: warp w handles k32 chunks kt = 2w, 2w+1
    const uint32_t base = smem_u32(swt);
    const uint32_t boff = ((lane & 7) + ((lane >> 4) & 1) * 8) * (WT_STRIDE * 2)
                        + ((lane >> 3) & 1) * 16;
#pragma unroll
    for (int t = 0; t < 2; t++) {
        const int kt = wid * 2 + t;            // k32 chunk 0..15
#pragma unroll
        for (int s = 0; s < 2; s++) {          // k16 sub
            const int k16 = kt * 2 + s;
#pragma unroll
            for (int g = 0; g < 4; g++) {      // 16-row n group
                uint32_t r[4];
                ldsm4(r, base + g * 16 * (WT_STRIDE * 2) + k16 * 32 + boff);
                g_w1frag[((nb * 32 + k16) * 4 + g) * 32 + lane] =
                    make_uint4(r[0], r[1], r[2], r[3]);
            }
        }
    }
}

// ---------------- prepass: enc f32 -> A fragments (f16) ----------------------
__global__ __launch_bounds__(256)
void encfrag_kernel(const float* __restrict__ enc) {
    __shared__ __align__(16) char sA[8][32 * 80];
    const int lane = threadIdx.x & 31, wid = threadIdx.x >> 5;
    const int mb = blockIdx.x * 8 + wid;
    const float* src = enc + (size_t)mb * 32 * D_;
    char* ws = sA[wid];
    const uint32_t base = smem_u32(ws);
    const uint32_t aoff = ((lane & 7) + ((lane >> 3) & 1) * 8) * 80 + ((lane >> 4) & 1) * 16;
    const int r0 = lane >> 3;        // 0..3
    const int c0 = (lane & 7) * 4;   // f32 col within k32 chunk

    for (int kt = 0; kt < 16; kt++) {
        const int k0 = kt * 32;
#pragma unroll
        for (int i = 0; i < 8; i++) {
            const int row = r0 + i * 4;
            float4 f = *(const float4*)(src + (size_t)row * D_ + k0 + c0);
            half2 h0 = __floats2half2_rn(f.x, f.y);
            half2 h1 = __floats2half2_rn(f.z, f.w);
            *(uint2*)(ws + row * 80 + c0 * 2) = make_uint2(h2u(h0), h2u(h1));
        }
        __syncwarp();
#pragma unroll
        for (int s = 0; s < 2; s++)
#pragma unroll
            for (int g = 0; g < 2; g++) {
                uint32_t r[4];
                ldsm4(r, base + g * 16 * 80 + s * 32 + aoff);
                g_encfrag[(((size_t)mb * 32 + kt * 2 + s) * 2 + g) * 32 + lane] =
                    make_uint4(r[0], r[1], r[2], r[3]);
            }
        __syncwarp();
    }
}

__global__ void hd_kernel(const float* __restrict__ dec,
                          const float* __restrict__ W2,
                          const float* __restrict__ b2) {
    __shared__ float ds[D_];
    int b = blockIdx.x;
    int u = threadIdx.x;
    ds[u] = dec[b * D_ + u];
    __syncthreads();
    float a = b2[u];
#pragma unroll 8
    for (int k = 0; k < D_; k++) a = fmaf(ds[k], W2[k * U_ + u], a);
    g_hd[b * U_ + u] = a;
}

// ---------------- main score kernel: B smem ring, A direct LDG ---------------
// B stage = 512 uint4 (8KB): [sub(2)][nbLocal(2)][g(4)][lane(32)]
#define STG_U4 512
#define SMEM_STG_BYTES (STAGES * STG_U4 * 16)  // 32768
#define SMEM_DYN_TOTAL (SMEM_STG_BYTES + 3 * 128 * 4)

__global__ __launch_bounds__(256, 2)
void score_pipe_kernel(const float* __restrict__ b1, const float* __restrict__ V) {
    extern __shared__ __align__(16) char smem[];
    uint4* stg = (uint4*)smem;
    float* cpre = (float*)(smem + SMEM_STG_BYTES);
    float* vpre = cpre + 128;
    float* ssum = vpre + 128;

    const int tid = threadIdx.x, lane = tid & 31, wid = tid >> 5;
    const int wm = wid >> 1, wn = wid & 1;
    const int n0 = blockIdx.x * 128, m0 = blockIdx.y * 128, b = m0 >> 11;

    if (tid < 128) {
        cpre[tid] = b1[n0 + tid] + g_hd[b * U_ + n0 + tid];
        vpre[tid] = V[n0 + tid];
        ssum[tid] = 0.0f;
    }

    const uint4* bsrc = g_w1frag +
        (((size_t)(blockIdx.x * 2 + (tid >> 7)) * 32) * 4 + ((tid >> 5) & 3)) * 32 + (tid & 31);
    const uint4* Ap = g_encfrag + (size_t)(blockIdx.y * 4 + wm) * 2048 + lane;

#pragma unroll
    for (int s = 0; s < 3; s++) {
        uint4* sp = stg + s * STG_U4;
        cp16(smem_u32(sp + tid),       bsrc + (size_t)(2 * s) * 128);
        cp16(smem_u32(sp + 256 + tid), bsrc + (size_t)(2 * s + 1) * 128);
        CP_COMMIT();
    }

    uint4 a00 = Ap[0],  a01 = Ap[32];
    uint4 a10 = Ap[64], a11 = Ap[96];

    float acc[2][8][4] = {};
    const int boff = wn * 128 + lane;

    int buf = 0, pbuf = 3;
#pragma unroll 4
    for (int st = 0; st < 16; st++) {
        CP_WAIT2();
        __syncthreads();

        if (st + 3 < 16) {
            uint4* sp = stg + pbuf * STG_U4;
            cp16(smem_u32(sp + tid),       bsrc + (size_t)(2 * (st + 3)) * 128);
            cp16(smem_u32(sp + 256 + tid), bsrc + (size_t)(2 * (st + 3) + 1) * 128);
        }
        CP_COMMIT();

        const uint4* sb = stg + buf * STG_U4;

        {  // sub 0
            uint4 f0 = sb[boff], f1 = sb[boff + 32], f2 = sb[boff + 64], f3 = sb[boff + 96];
            const uint32_t* A0 = (const uint32_t*)&a00;
            const uint32_t* A1 = (const uint32_t*)&a01;
            const uint32_t* B0 = (const uint32_t*)&f0;
            const uint32_t* B1 = (const uint32_t*)&f1;
            const uint32_t* B2 = (const uint32_t*)&f2;
            const uint32_t* B3 = (const uint32_t*)&f3;
            mma16816(acc[0][0], A0, B0); mma16816(acc[0][1], A0, B0 + 2);
            mma16816(acc[1][0], A1, B0); mma16816(acc[1][1], A1, B0 + 2);
            mma16816(acc[0][2], A0, B1); mma16816(acc[0][3], A0, B1 + 2);
            mma16816(acc[1][2], A1, B1); mma16816(acc[1][3], A1, B1 + 2);
            mma16816(acc[0][4], A0, B2); mma16816(acc[0][5], A0, B2 + 2);
            mma16816(acc[1][4], A1, B2); mma16816(acc[1][5], A1, B2 + 2);
            mma16816(acc[0][6], A0, B3); mma16816(acc[0][7], A0, B3 + 2);
            mma16816(acc[1][6], A1, B3); mma16816(acc[1][7], A1, B3 + 2);
        }
        if (st < 15) {
            a00 = Ap[(size_t)(2 * st + 2) * 64];
            a01 = Ap[(size_t)(2 * st + 2) * 64 + 32];
        }

        {  // sub 1
            const uint4* sb1 = sb + 256;
            uint4 f0 = sb1[boff], f1 = sb1[boff + 32], f2 = sb1[boff + 64], f3 = sb1[boff + 96];
            const uint32_t* A0 = (const uint32_t*)&a10;
            const uint32_t* A1 = (const uint32_t*)&a11;
            const uint32_t* B0 = (const uint32_t*)&f0;
            const uint32_t* B1 = (const uint32_t*)&f1;
            const uint32_t* B2 = (const uint32_t*)&f2;
            const uint32_t* B3 = (const uint32_t*)&f3;
            mma16816(acc[0][0], A0, B0); mma16816(acc[0][1], A0, B0 + 2);
            mma16816(acc[1][0], A1, B0); mma16816(acc[1][1], A1, B0 + 2);
            mma16816(acc[0][2], A0, B1); mma16816(acc[0][3], A0, B1 + 2);
            mma16816(acc[1][2], A1, B1); mma16816(acc[1][3], A1, B1 + 2);
            mma16816(acc[0][4], A0, B2); mma16816(acc[0][5], A0, B2 + 2);
            mma16816(acc[1][4], A1, B2); mma16816(acc[1][5], A1, B2 + 2);
            mma16816(acc[0][6], A0, B3); mma16816(acc[0][7], A0, B3 + 2);
            mma16816(acc[1][6], A1, B3); mma16816(acc[1][7], A1, B3 + 2);
        }
        if (st < 15) {
            a10 = Ap[(size_t)(2 * st + 3) * 64];
            a11 = Ap[(size_t)(2 * st + 3) * 64 + 32];
        }

        buf = (buf + 1) & 3;
        pbuf = (pbuf + 1) & 3;
    }

    __syncthreads();

    // ---- epilogue: tanh + V-dot, reduce to row partials ----
    const int g = lane >> 2, tg = lane & 3;
    const int n_base = wn * 64;
    float p[2][2] = {{0.0f, 0.0f}, {0.0f, 0.0f}};
#pragma unroll
    for (int mf = 0; mf < 2; mf++) {
#pragma unroll
        for (int nf = 0; nf < 8; nf++) {
            const int c0 = n_base + nf * 8 + tg * 2;
            const float v0 = vpre[c0], v1 = vpre[c0 + 1];
            const float k0 = cpre[c0], k1 = cpre[c0 + 1];
            p[mf][0] += v0 * tanhf(acc[mf][nf][0] + k0) + v1 * tanhf(acc[mf][nf][1] + k1);
            p[mf][1] += v0 * tanhf(acc[mf][nf][2] + k0) + v1 * tanhf(acc[mf][nf][3] + k1);
        }
    }
#pragma unroll
    for (int mf = 0; mf < 2; mf++)
#pragma unroll
        for (int h = 0; h < 2; h++) {
            float s = p[mf][h];
            s += __shfl_xor_sync(0xffffffffu, s, 1);
            s += __shfl_xor_sync(0xffffffffu, s, 2);
            if (tg == 0) atomicAdd(&ssum[wm * 32 + mf * 16 + h * 8 + g], s);
        }
    __syncthreads();
    if (tid < 128) g_spart[(size_t)blockIdx.x * M_TOT + m0 + tid] = ssum[tid];
}

// ---------------- softmax stats (combines 4 partials) ------------------------
__global__ void stats_kernel() {
    const int b = blockIdx.x;
    const int tid = threadIdx.x;  // 256
    __shared__ float red[256];
    float m = -1e30f;
    for (int s = tid; s < S_; s += 256) {
        const int i = b * S_ + s;
        const float v = g_spart[i] + g_spart[M_TOT + i] + g_spart[2 * M_TOT + i] + g_spart[3 * M_TOT + i];
        g_scores[i] = v;
        m = fmaxf(m, v);
    }
    red[tid] = m;
    __syncthreads();
    for (int o = 128; o; o >>= 1) {
        if (tid < o) red[tid] = fmaxf(red[tid], red[tid + o]);
        __syncthreads();
    }
    const float mx = red[0];
    __syncthreads();
    float sum = 0.0f;
    for (int s = tid; s < S_; s += 256) sum += expf(g_scores[b * S_ + s] - mx);
    red[tid] = sum;
    __syncthreads();
    for (int o = 128; o; o >>= 1) {
        if (tid < o) red[tid] += red[tid + o];
        __syncthreads();
    }
    if (tid == 0) {
        g_max[b] = mx;
        g_invsum[b] = 1.0f / red[0];
    }
}

// ---------------- context: per-chunk partials (plain stores), then reduce ----
__global__ void cpart_kernel(const float* __restrict__ enc) {
    __shared__ float attn[128];
    const int chunk = blockIdx.x;   // 0..15
    const int b = blockIdx.y;
    const int s0 = chunk * 128;
    const int tid = threadIdx.x;    // 128
    attn[tid] = expf(g_scores[b * S_ + s0 + tid] - g_max[b]) * g_invsum[b];
    __syncthreads();
    const float4* base = (const float4*)(enc + ((size_t)b * S_ + s0) * D_);
    float ax = 0.0f, ay = 0.0f, az = 0.0f, aw = 0.0f;
#pragma unroll 4
    for (int s = 0; s < 128; s++) {
        const float w = attn[s];
        const float4 v = base[(size_t)s * 128 + tid];
        ax = fmaf(w, v.x, ax);
        ay = fmaf(w, v.y, ay);
        az = fmaf(w, v.z, az);
        aw = fmaf(w, v.w, aw);
    }
    ((float4*)g_ctx)[((size_t)chunk * B_ + b) * 128 + tid] = make_float4(ax, ay, az, aw);
}

__global__ void cfinal_kernel(float* __restrict__ out) {
    const int b = blockIdx.x;       // 0..63
    const int tid = threadIdx.x;    // 128
    float4 acc = make_float4(0.f, 0.f, 0.f, 0.f);
#pragma unroll
    for (int c = 0; c < NCHUNK; c++) {
        const float4 v = ((const float4*)g_ctx)[((size_t)c * B_ + b) * 128 + tid];
        acc.x += v.x; acc.y += v.y; acc.z += v.z; acc.w += v.w;
    }
    ((float4*)out)[b * 128 + tid] = acc;
}

// ---------------- launch ------------------------------------------------------
extern "C" void kernel_launch(void* const* d_in, const int* in_sizes, int n_in,
                              void* d_out, int out_size) {
    const float* enc = (const float*)d_in[0];
    const float* dec = (const float*)d_in[1];
    const float* W1  = (const float*)d_in[2];
    const float* b1  = (const float*)d_in[3];
    const float* W2  = (const float*)d_in[4];
    const float* b2  = (const float*)d_in[5];
    const float* V   = (const float*)d_in[6];
    // d_in[7] = bv: constant shift, cancels in softmax.
    float* out = (float*)d_out;

    cudaFuncSetAttribute(score_pipe_kernel,
                         cudaFuncAttributeMaxDynamicSharedMemorySize, SMEM_DYN_TOTAL);
    cudaFuncSetAttribute(wfrag_kernel,
                         cudaFuncAttributeMaxDynamicSharedMemorySize, WT_SMEM);

    wfrag_kernel<<<8, 256, WT_SMEM>>>(W1);                                   // idx 0
    encfrag_kernel<<<MB_CNT / 8, 256>>>(enc);                                // idx 1
    hd_kernel<<<B_, U_>>>(dec, W2, b2);                                      // idx 2
    score_pipe_kernel<<<dim3(4, M_TOT / 128), 256, SMEM_DYN_TOTAL>>>(b1, V); // idx 3 (profiled)
    stats_kernel<<<B_, 256>>>();                                             // idx 4
    cpart_kernel<<<dim3(NCHUNK, B_), 128>>>(enc);                            // idx 5
    cfinal_kernel<<<B_, 128>>>(out);                                         // idx 6
}